// round 2
// baseline (speedup 1.0000x reference)
#include <cuda_runtime.h>

#define N_NODES   100000
#define N_EDGES   3200000
#define NUM_GRAPHS 128
#define HID       64
#define IN_DIM    15

// ---------------- scratch (device globals; no allocation allowed) -----------
__device__ __align__(16) float g_hpre[N_NODES * HID];
__device__ __align__(16) float g_aggA[N_NODES * HID];
__device__ __align__(16) float g_aggB[N_NODES * HID];
__device__ float g_norm[N_EDGES];
__device__ int   g_src[N_EDGES];
__device__ int   g_dst[N_EDGES];
__device__ int   g_deg[N_NODES];
__device__ float g_dis[N_NODES];
__device__ float g_invdeg[N_NODES];
__device__ float g_cnt[NUM_GRAPHS];
__device__ int   g_e32;   // 1 if edge_index is int32, 0 if int64
__device__ int   g_b32;   // 1 if batch is int32, 0 if int64

// ---------------- dtype detection -------------------------------------------
// The reference asks for int64 but JAX canonicalizes to int32 unless x64 is
// enabled. Detect by sampling the buffer interpreted as int64 (only within the
// first half, so reads stay in-bounds even for an int32 buffer): packed int32
// pairs produce values ~hi*2^32, far outside the valid index range.
__global__ void gnn_detect(const void* edges, const void* batch) {
    __shared__ int se, sb;
    if (threadIdx.x == 0) { se = 0; sb = 0; }
    __syncthreads();
    for (int i = threadIdx.x; i < 2048; i += 256) {
        long long vi = (long long)i * (N_EDGES / 2048);   // < N_EDGES
        long long v = ((const long long*)edges)[vi];
        if (v < 0 || v >= N_NODES) { atomicOr(&se, 1); break; }
    }
    for (int i = threadIdx.x; i < 2048; i += 256) {
        long long vi = (long long)i * ((N_NODES / 2) / 2048);  // < N_NODES/2
        long long v = ((const long long*)batch)[vi];
        if (v < 0 || v >= NUM_GRAPHS) { atomicOr(&sb, 1); break; }
    }
    __syncthreads();
    if (threadIdx.x == 0) { g_e32 = se; g_b32 = sb; }
}

__device__ __forceinline__ int edge_at(const void* edges, long long i) {
    return g_e32 ? ((const int*)edges)[i] : (int)((const long long*)edges)[i];
}
__device__ __forceinline__ int batch_at(const void* batch, int v) {
    return g_b32 ? ((const int*)batch)[v] : (int)((const long long*)batch)[v];
}

// ---------------- normalization ---------------------------------------------
__global__ void gnn_deg_init() {
    int v = blockIdx.x * blockDim.x + threadIdx.x;
    if (v < N_NODES) g_deg[v] = 1;  // self loop
}

__global__ void gnn_deg_count(const void* __restrict__ edges) {
    int e = blockIdx.x * blockDim.x + threadIdx.x;
    if (e < N_EDGES) {
        int d = edge_at(edges, (long long)N_EDGES + e);
        atomicAdd(&g_deg[d], 1);
    }
}

__global__ void gnn_dis() {
    int v = blockIdx.x * blockDim.x + threadIdx.x;
    if (v < N_NODES) {
        float d = (float)g_deg[v];
        g_dis[v]    = rsqrtf(d);
        g_invdeg[v] = 1.0f / d;
    }
}

__global__ void gnn_norm(const void* __restrict__ edges) {
    int e = blockIdx.x * blockDim.x + threadIdx.x;
    if (e < N_EDGES) {
        int s = edge_at(edges, e);
        int d = edge_at(edges, (long long)N_EDGES + e);
        g_src[e]  = s;
        g_dst[e]  = d;
        g_norm[e] = g_dis[s] * g_dis[d];
    }
}

// ---------------- linear (+ optional bias+relu on input) + self-loop init ---
// Block: 256 threads, 32 nodes per block. Each thread computes 8 output cols
// for one node. Writes hpre and initializes agg = hpre * invdeg (self loop).
template <int K, bool PRE>
__global__ void gnn_linear(const float* __restrict__ in,
                           const float* __restrict__ W,
                           const float* __restrict__ bias_prev,
                           float* __restrict__ hpre,
                           float* __restrict__ agg) {
    __shared__ float Wsh[K * HID];
    __shared__ float insh[32][K + 1];
    const int tid = threadIdx.x;
    for (int i = tid; i < K * HID; i += 256) Wsh[i] = W[i];

    const int base = blockIdx.x * 32;
    for (int i = tid; i < 32 * K; i += 256) {
        int vl = i / K;
        int k  = i - vl * K;
        int v  = base + vl;
        float val = 0.0f;
        if (v < N_NODES) {
            val = in[v * K + k];
            if (PRE) val = fmaxf(val + bias_prev[k], 0.0f);
        }
        insh[vl][k] = val;
    }
    __syncthreads();

    const int vl = tid >> 3;
    const int cb = (tid & 7) * 8;
    float acc[8];
#pragma unroll
    for (int j = 0; j < 8; j++) acc[j] = 0.0f;
#pragma unroll 16
    for (int k = 0; k < K; k++) {
        float a = insh[vl][k];
#pragma unroll
        for (int j = 0; j < 8; j++) acc[j] += a * Wsh[k * HID + cb + j];
    }
    const int v = base + vl;
    if (v < N_NODES) {
        float id = g_invdeg[v];
#pragma unroll
        for (int j = 0; j < 8; j++) {
            hpre[v * HID + cb + j] = acc[j];
            agg [v * HID + cb + j] = acc[j] * id;
        }
    }
}

// ---------------- edge scatter: agg[dst] += hpre[src] * norm ----------------
// 16 threads per edge, one float4 each; red.global.add.v4.f32 (no return).
__global__ void gnn_scatter(const float4* __restrict__ hp,
                            float* __restrict__ agg) {
    unsigned idx = blockIdx.x * blockDim.x + threadIdx.x;
    int e = idx >> 4;
    int c = idx & 15;
    if (e >= N_EDGES) return;
    int   s = g_src[e];
    int   d = g_dst[e];
    float n = g_norm[e];
    float4 h = hp[s * 16 + c];
    float* p = &agg[d * HID + c * 4];
    asm volatile("red.global.add.v4.f32 [%0], {%1, %2, %3, %4};"
                 :: "l"(p), "f"(h.x * n), "f"(h.y * n), "f"(h.z * n), "f"(h.w * n)
                 : "memory");
}

// ---------------- pooling ----------------------------------------------------
__global__ void gnn_zero_out(float* __restrict__ out) {
    int i = blockIdx.x * blockDim.x + threadIdx.x;
    if (i < NUM_GRAPHS * HID) out[i] = 0.0f;
    if (i < NUM_GRAPHS) g_cnt[i] = 0.0f;
}

__global__ void gnn_pool(const float4* __restrict__ agg,
                         const float4* __restrict__ bias4,
                         const void* __restrict__ batch,
                         float* __restrict__ out) {
    unsigned idx = blockIdx.x * blockDim.x + threadIdx.x;
    int v = idx >> 4;
    int c = idx & 15;
    if (v >= N_NODES) return;
    int g = batch_at(batch, v);
    float4 a = agg[v * 16 + c];
    float4 b = bias4[c];
    float x0 = fmaxf(a.x + b.x, 0.0f);
    float x1 = fmaxf(a.y + b.y, 0.0f);
    float x2 = fmaxf(a.z + b.z, 0.0f);
    float x3 = fmaxf(a.w + b.w, 0.0f);
    float* p = &out[g * HID + c * 4];
    asm volatile("red.global.add.v4.f32 [%0], {%1, %2, %3, %4};"
                 :: "l"(p), "f"(x0), "f"(x1), "f"(x2), "f"(x3)
                 : "memory");
    if (c == 0) atomicAdd(&g_cnt[g], 1.0f);
}

__global__ void gnn_div(float* __restrict__ out) {
    int i = blockIdx.x * blockDim.x + threadIdx.x;
    if (i < NUM_GRAPHS * HID) {
        int g = i >> 6;
        out[i] /= fmaxf(g_cnt[g], 1.0f);
    }
}

// ---------------- host -------------------------------------------------------
extern "C" void kernel_launch(void* const* d_in, const int* in_sizes, int n_in,
                              void* d_out, int out_size) {
    const float* x     = (const float*)d_in[0];
    const float* w1    = (const float*)d_in[1];
    const float* b1    = (const float*)d_in[2];
    const float* w2    = (const float*)d_in[3];
    const float* b2    = (const float*)d_in[4];
    const float* w3    = (const float*)d_in[5];
    const float* b3    = (const float*)d_in[6];
    const float* w4    = (const float*)d_in[7];
    const float* b4    = (const float*)d_in[8];
    const void*  edges = d_in[9];
    const void*  batch = d_in[10];
    float* out = (float*)d_out;

    void *p_hpre, *p_aggA, *p_aggB;
    cudaGetSymbolAddress(&p_hpre, g_hpre);
    cudaGetSymbolAddress(&p_aggA, g_aggA);
    cudaGetSymbolAddress(&p_aggB, g_aggB);
    float* hpre = (float*)p_hpre;
    float* aggA = (float*)p_aggA;
    float* aggB = (float*)p_aggB;

    const int TB = 256;
    // dtype detection + normalization
    gnn_detect   <<<1, 256>>>(edges, batch);
    gnn_deg_init <<<(N_NODES + TB - 1) / TB, TB>>>();
    gnn_deg_count<<<(N_EDGES + TB - 1) / TB, TB>>>(edges);
    gnn_dis      <<<(N_NODES + TB - 1) / TB, TB>>>();
    gnn_norm     <<<(N_EDGES + TB - 1) / TB, TB>>>(edges);

    const int linB  = (N_NODES + 31) / 32;
    const unsigned scatT = (unsigned)N_EDGES * 16u;
    const int scatB = (int)((scatT + TB - 1) / TB);

    // layer 1: x -> hpre, aggA
    gnn_linear<IN_DIM, false><<<linB, TB>>>(x, w1, nullptr, hpre, aggA);
    gnn_scatter<<<scatB, TB>>>((const float4*)hpre, aggA);
    // layer 2: relu(aggA + b1) -> hpre, aggB
    gnn_linear<HID, true><<<linB, TB>>>(aggA, w2, b1, hpre, aggB);
    gnn_scatter<<<scatB, TB>>>((const float4*)hpre, aggB);
    // layer 3: relu(aggB + b2) -> hpre, aggA
    gnn_linear<HID, true><<<linB, TB>>>(aggB, w3, b2, hpre, aggA);
    gnn_scatter<<<scatB, TB>>>((const float4*)hpre, aggA);
    // layer 4: relu(aggA + b3) -> hpre, aggB
    gnn_linear<HID, true><<<linB, TB>>>(aggA, w4, b3, hpre, aggB);
    gnn_scatter<<<scatB, TB>>>((const float4*)hpre, aggB);

    // pooling: mean over relu(aggB + b4) per graph
    gnn_zero_out<<<(NUM_GRAPHS * HID + TB - 1) / TB, TB>>>(out);
    const unsigned poolT = (unsigned)N_NODES * 16u;
    gnn_pool<<<(int)((poolT + TB - 1) / TB), TB>>>(
        (const float4*)aggB, (const float4*)b4, batch, out);
    gnn_div<<<(NUM_GRAPHS * HID + TB - 1) / TB, TB>>>(out);
}

// round 3
// speedup vs baseline: 1.3348x; 1.3348x over previous
#include <cuda_runtime.h>

#define N_NODES    100000
#define N_EDGES    3200000
#define NUM_GRAPHS 128
#define HID        64
#define IN_DIM     15
#define NBLK       ((N_NODES + 255) / 256)   // 391 scan blocks

// ---------------- scratch (device globals; no allocation allowed) -----------
__device__ __align__(16) float g_hpre[N_NODES * HID];
__device__ __align__(16) float g_aggA[N_NODES * HID];
__device__ __align__(16) float g_aggB[N_NODES * HID];
__device__ int   g_csrc [N_EDGES];   // CSR (by dst): source node per slot
__device__ float g_cnorm[N_EDGES];   // CSR: edge norm per slot
__device__ int   g_edeg  [N_NODES];  // in-degree (edges only)
__device__ int   g_pre   [N_NODES];  // per-block exclusive prescan
__device__ int   g_rowptr[N_NODES];
__device__ int   g_fill  [N_NODES];
__device__ int   g_bsum[NBLK];
__device__ int   g_boff[NBLK];
__device__ float g_dis[N_NODES];
__device__ float g_invdeg[N_NODES];
__device__ float g_cnt[NUM_GRAPHS];
__device__ int   g_e32;   // 1 if edge_index is int32
__device__ int   g_b32;   // 1 if batch is int32

// ---------------- dtype detection -------------------------------------------
__global__ void gnn_detect(const void* edges, const void* batch) {
    __shared__ int se, sb;
    if (threadIdx.x == 0) { se = 0; sb = 0; }
    __syncthreads();
    for (int i = threadIdx.x; i < 2048; i += 256) {
        long long vi = (long long)i * (N_EDGES / 2048);
        long long v = ((const long long*)edges)[vi];
        if (v < 0 || v >= N_NODES) { atomicOr(&se, 1); break; }
    }
    for (int i = threadIdx.x; i < 2048; i += 256) {
        long long vi = (long long)i * ((N_NODES / 2) / 2048);
        long long v = ((const long long*)batch)[vi];
        if (v < 0 || v >= NUM_GRAPHS) { atomicOr(&sb, 1); break; }
    }
    __syncthreads();
    if (threadIdx.x == 0) { g_e32 = se; g_b32 = sb; }
}

__device__ __forceinline__ int edge_at(const void* edges, long long i) {
    return g_e32 ? ((const int*)edges)[i] : (int)((const long long*)edges)[i];
}
__device__ __forceinline__ int batch_at(const void* batch, int v) {
    return g_b32 ? ((const int*)batch)[v] : (int)((const long long*)batch)[v];
}

// ---------------- degree / normalization ------------------------------------
__global__ void gnn_deg_zero() {
    int v = blockIdx.x * blockDim.x + threadIdx.x;
    if (v < N_NODES) g_edeg[v] = 0;
}

__global__ void gnn_deg_count(const void* __restrict__ edges) {
    int e = blockIdx.x * blockDim.x + threadIdx.x;
    if (e < N_EDGES) {
        int d = edge_at(edges, (long long)N_EDGES + e);
        atomicAdd(&g_edeg[d], 1);
    }
}

__global__ void gnn_dis() {
    int v = blockIdx.x * blockDim.x + threadIdx.x;
    if (v < N_NODES) {
        float d = (float)(g_edeg[v] + 1);  // + self loop
        g_dis[v]    = rsqrtf(d);
        g_invdeg[v] = 1.0f / d;
    }
}

// ---------------- exclusive scan of g_edeg -> g_rowptr -----------------------
__global__ void gnn_scan1() {
    __shared__ int s[256];
    int t = threadIdx.x;
    int i = blockIdx.x * 256 + t;
    int v = (i < N_NODES) ? g_edeg[i] : 0;
    s[t] = v; __syncthreads();
    for (int off = 1; off < 256; off <<= 1) {
        int add = (t >= off) ? s[t - off] : 0;
        __syncthreads();
        s[t] += add;
        __syncthreads();
    }
    if (i < N_NODES) g_pre[i] = s[t] - v;   // exclusive
    if (t == 255) g_bsum[blockIdx.x] = s[255];
}

__global__ void gnn_scan2() {
    __shared__ int s[512];
    int t = threadIdx.x;
    int v = (t < NBLK) ? g_bsum[t] : 0;
    s[t] = v; __syncthreads();
    for (int off = 1; off < 512; off <<= 1) {
        int add = (t >= off) ? s[t - off] : 0;
        __syncthreads();
        s[t] += add;
        __syncthreads();
    }
    if (t < NBLK) g_boff[t] = s[t] - v;     // exclusive
}

__global__ void gnn_scan3() {
    int i = blockIdx.x * blockDim.x + threadIdx.x;
    if (i < N_NODES) {
        g_rowptr[i] = g_pre[i] + g_boff[blockIdx.x];
        g_fill[i]   = 0;
    }
}

// ---------------- CSR fill ----------------------------------------------------
__global__ void gnn_csr_fill(const void* __restrict__ edges) {
    int e = blockIdx.x * blockDim.x + threadIdx.x;
    if (e < N_EDGES) {
        int s = edge_at(edges, e);
        int d = edge_at(edges, (long long)N_EDGES + e);
        int slot = g_rowptr[d] + atomicAdd(&g_fill[d], 1);
        g_csrc [slot] = s;
        g_cnorm[slot] = g_dis[s] * g_dis[d];
    }
}

// ---------------- linear (+ optional bias+relu on input) --------------------
template <int K, bool PRE>
__global__ void gnn_linear(const float* __restrict__ in,
                           const float* __restrict__ W,
                           const float* __restrict__ bias_prev,
                           float* __restrict__ hpre) {
    __shared__ float Wsh[K * HID];
    __shared__ float insh[32][K + 1];
    const int tid = threadIdx.x;
    for (int i = tid; i < K * HID; i += 256) Wsh[i] = W[i];

    const int base = blockIdx.x * 32;
    for (int i = tid; i < 32 * K; i += 256) {
        int vl = i / K;
        int k  = i - vl * K;
        int v  = base + vl;
        float val = 0.0f;
        if (v < N_NODES) {
            val = in[v * K + k];
            if (PRE) val = fmaxf(val + bias_prev[k], 0.0f);
        }
        insh[vl][k] = val;
    }
    __syncthreads();

    const int vl = tid >> 3;
    const int cb = (tid & 7) * 8;
    float acc[8];
#pragma unroll
    for (int j = 0; j < 8; j++) acc[j] = 0.0f;
#pragma unroll 16
    for (int k = 0; k < K; k++) {
        float a = insh[vl][k];
#pragma unroll
        for (int j = 0; j < 8; j++) acc[j] += a * Wsh[k * HID + cb + j];
    }
    const int v = base + vl;
    if (v < N_NODES) {
#pragma unroll
        for (int j = 0; j < 8; j++) hpre[v * HID + cb + j] = acc[j];
    }
}

// ---------------- gather: agg[v] = sum_{e in row v} hpre[src]*norm + self ----
// One warp per destination node; lane owns 2 columns (float2). Edge meta is
// loaded 32-at-a-time and broadcast via shuffle; predicated unrolled inner
// loop keeps high MLP without wasted tail loads.
__global__ void __launch_bounds__(256) gnn_gather(const float2* __restrict__ hp2,
                                                  float2* __restrict__ agg2) {
    int warp = (blockIdx.x * blockDim.x + threadIdx.x) >> 5;
    int lane = threadIdx.x & 31;
    if (warp >= N_NODES) return;
    const int v   = warp;
    const int beg = g_rowptr[v];
    const int end = beg + g_edeg[v];

    float2 hs = hp2[v * 32 + lane];
    float  id = g_invdeg[v];
    float ax = hs.x * id;
    float ay = hs.y * id;

    for (int base = beg; base < end; base += 32) {
        int   s  = 0;
        float nn = 0.0f;
        if (base + lane < end) {
            s  = g_csrc [base + lane];
            nn = g_cnorm[base + lane];
        }
        const int n_in = min(32, end - base);
#pragma unroll
        for (int j = 0; j < 32; j++) {
            if (j < n_in) {
                int   ss = __shfl_sync(0xffffffffu, s,  j);
                float nj = __shfl_sync(0xffffffffu, nn, j);
                float2 hh = hp2[ss * 32 + lane];
                ax = fmaf(hh.x, nj, ax);
                ay = fmaf(hh.y, nj, ay);
            }
        }
    }
    agg2[v * 32 + lane] = make_float2(ax, ay);
}

// ---------------- pooling ----------------------------------------------------
__global__ void gnn_zero_out(float* __restrict__ out) {
    int i = blockIdx.x * blockDim.x + threadIdx.x;
    if (i < NUM_GRAPHS * HID) out[i] = 0.0f;
    if (i < NUM_GRAPHS) g_cnt[i] = 0.0f;
}

__global__ void gnn_pool(const float4* __restrict__ agg,
                         const float4* __restrict__ bias4,
                         const void* __restrict__ batch,
                         float* __restrict__ out) {
    unsigned idx = blockIdx.x * blockDim.x + threadIdx.x;
    int v = idx >> 4;
    int c = idx & 15;
    if (v >= N_NODES) return;
    int g = batch_at(batch, v);
    float4 a = agg[v * 16 + c];
    float4 b = bias4[c];
    float x0 = fmaxf(a.x + b.x, 0.0f);
    float x1 = fmaxf(a.y + b.y, 0.0f);
    float x2 = fmaxf(a.z + b.z, 0.0f);
    float x3 = fmaxf(a.w + b.w, 0.0f);
    float* p = &out[g * HID + c * 4];
    asm volatile("red.global.add.v4.f32 [%0], {%1, %2, %3, %4};"
                 :: "l"(p), "f"(x0), "f"(x1), "f"(x2), "f"(x3)
                 : "memory");
    if (c == 0) atomicAdd(&g_cnt[g], 1.0f);
}

__global__ void gnn_div(float* __restrict__ out) {
    int i = blockIdx.x * blockDim.x + threadIdx.x;
    if (i < NUM_GRAPHS * HID) {
        int g = i >> 6;
        out[i] /= fmaxf(g_cnt[g], 1.0f);
    }
}

// ---------------- host -------------------------------------------------------
extern "C" void kernel_launch(void* const* d_in, const int* in_sizes, int n_in,
                              void* d_out, int out_size) {
    const float* x     = (const float*)d_in[0];
    const float* w1    = (const float*)d_in[1];
    const float* b1    = (const float*)d_in[2];
    const float* w2    = (const float*)d_in[3];
    const float* b2    = (const float*)d_in[4];
    const float* w3    = (const float*)d_in[5];
    const float* b3    = (const float*)d_in[6];
    const float* w4    = (const float*)d_in[7];
    const float* b4    = (const float*)d_in[8];
    const void*  edges = d_in[9];
    const void*  batch = d_in[10];
    float* out = (float*)d_out;

    void *p_hpre, *p_aggA, *p_aggB;
    cudaGetSymbolAddress(&p_hpre, g_hpre);
    cudaGetSymbolAddress(&p_aggA, g_aggA);
    cudaGetSymbolAddress(&p_aggB, g_aggB);
    float* hpre = (float*)p_hpre;
    float* aggA = (float*)p_aggA;
    float* aggB = (float*)p_aggB;

    const int TB = 256;
    const int nodeB = (N_NODES + TB - 1) / TB;
    const int edgeB = (N_EDGES + TB - 1) / TB;

    // dtype detection + degree/norm + CSR build
    gnn_detect   <<<1, 256>>>(edges, batch);
    gnn_deg_zero <<<nodeB, TB>>>();
    gnn_deg_count<<<edgeB, TB>>>(edges);
    gnn_dis      <<<nodeB, TB>>>();
    gnn_scan1    <<<NBLK, 256>>>();
    gnn_scan2    <<<1, 512>>>();
    gnn_scan3    <<<NBLK, 256>>>();
    gnn_csr_fill <<<edgeB, TB>>>(edges);

    const int linB  = (N_NODES + 31) / 32;
    const int gatB  = (N_NODES * 32 + TB - 1) / TB;  // one warp per node

    // layer 1
    gnn_linear<IN_DIM, false><<<linB, TB>>>(x, w1, nullptr, hpre);
    gnn_gather<<<gatB, TB>>>((const float2*)hpre, (float2*)aggA);
    // layer 2
    gnn_linear<HID, true><<<linB, TB>>>(aggA, w2, b1, hpre);
    gnn_gather<<<gatB, TB>>>((const float2*)hpre, (float2*)aggB);
    // layer 3
    gnn_linear<HID, true><<<linB, TB>>>(aggB, w3, b2, hpre);
    gnn_gather<<<gatB, TB>>>((const float2*)hpre, (float2*)aggA);
    // layer 4
    gnn_linear<HID, true><<<linB, TB>>>(aggA, w4, b3, hpre);
    gnn_gather<<<gatB, TB>>>((const float2*)hpre, (float2*)aggB);

    // pooling: mean over relu(aggB + b4) per graph
    gnn_zero_out<<<(NUM_GRAPHS * HID + TB - 1) / TB, TB>>>(out);
    const unsigned poolT = (unsigned)N_NODES * 16u;
    gnn_pool<<<(int)((poolT + TB - 1) / TB), TB>>>(
        (const float4*)aggB, (const float4*)b4, batch, out);
    gnn_div<<<(NUM_GRAPHS * HID + TB - 1) / TB, TB>>>(out);
}

// round 4
// speedup vs baseline: 1.3860x; 1.0383x over previous
#include <cuda_runtime.h>
#include <cuda_fp16.h>

#define N_NODES    100000
#define N_EDGES    3200000
#define NUM_GRAPHS 128
#define HID        64
#define IN_DIM     15
#define NBLK       ((N_NODES + 255) / 256)   // 391 scan blocks

// ---------------- scratch (device globals; no allocation allowed) -----------
__device__ __align__(16) __half2 g_hs[N_NODES * 32];   // scaled features fp16
__device__ __align__(16) float   g_aggA[N_NODES * HID];
__device__ __align__(16) float   g_aggB[N_NODES * HID];
__device__ int   g_csrc [N_EDGES];   // CSR (by dst): source node per slot
__device__ int   g_edeg  [N_NODES];  // in-degree (edges only)
__device__ int   g_pre   [N_NODES];
__device__ int   g_rowptr[N_NODES];
__device__ int   g_fill  [N_NODES];
__device__ int   g_bsum[NBLK];
__device__ int   g_boff[NBLK];
__device__ float g_dis[N_NODES];
__device__ float g_cnt[NUM_GRAPHS];
__device__ int   g_e32;   // 1 if edge_index is int32
__device__ int   g_b32;   // 1 if batch is int32

// ---------------- dtype detection -------------------------------------------
__global__ void gnn_detect(const void* edges, const void* batch) {
    __shared__ int se, sb;
    if (threadIdx.x == 0) { se = 0; sb = 0; }
    __syncthreads();
    for (int i = threadIdx.x; i < 2048; i += 256) {
        long long vi = (long long)i * (N_EDGES / 2048);
        long long v = ((const long long*)edges)[vi];
        if (v < 0 || v >= N_NODES) { atomicOr(&se, 1); break; }
    }
    for (int i = threadIdx.x; i < 2048; i += 256) {
        long long vi = (long long)i * ((N_NODES / 2) / 2048);
        long long v = ((const long long*)batch)[vi];
        if (v < 0 || v >= NUM_GRAPHS) { atomicOr(&sb, 1); break; }
    }
    __syncthreads();
    if (threadIdx.x == 0) { g_e32 = se; g_b32 = sb; }
}

__device__ __forceinline__ int edge_at(const void* edges, long long i) {
    return g_e32 ? ((const int*)edges)[i] : (int)((const long long*)edges)[i];
}
__device__ __forceinline__ int batch_at(const void* batch, int v) {
    return g_b32 ? ((const int*)batch)[v] : (int)((const long long*)batch)[v];
}

// ---------------- degree / normalization ------------------------------------
__global__ void gnn_deg_zero() {
    int v = blockIdx.x * blockDim.x + threadIdx.x;
    if (v < N_NODES) g_edeg[v] = 0;
}

__global__ void gnn_deg_count(const void* __restrict__ edges) {
    int e = blockIdx.x * blockDim.x + threadIdx.x;
    if (e < N_EDGES) {
        int d = edge_at(edges, (long long)N_EDGES + e);
        atomicAdd(&g_edeg[d], 1);
    }
}

__global__ void gnn_dis() {
    int v = blockIdx.x * blockDim.x + threadIdx.x;
    if (v < N_NODES) {
        float d = (float)(g_edeg[v] + 1);  // + self loop
        g_dis[v] = rsqrtf(d);
    }
}

// ---------------- exclusive scan of g_edeg -> g_rowptr -----------------------
__global__ void gnn_scan1() {
    __shared__ int s[256];
    int t = threadIdx.x;
    int i = blockIdx.x * 256 + t;
    int v = (i < N_NODES) ? g_edeg[i] : 0;
    s[t] = v; __syncthreads();
    for (int off = 1; off < 256; off <<= 1) {
        int add = (t >= off) ? s[t - off] : 0;
        __syncthreads();
        s[t] += add;
        __syncthreads();
    }
    if (i < N_NODES) g_pre[i] = s[t] - v;   // exclusive
    if (t == 255) g_bsum[blockIdx.x] = s[255];
}

__global__ void gnn_scan2() {
    __shared__ int s[512];
    int t = threadIdx.x;
    int v = (t < NBLK) ? g_bsum[t] : 0;
    s[t] = v; __syncthreads();
    for (int off = 1; off < 512; off <<= 1) {
        int add = (t >= off) ? s[t - off] : 0;
        __syncthreads();
        s[t] += add;
        __syncthreads();
    }
    if (t < NBLK) g_boff[t] = s[t] - v;     // exclusive
}

__global__ void gnn_scan3() {
    int i = blockIdx.x * blockDim.x + threadIdx.x;
    if (i < N_NODES) {
        g_rowptr[i] = g_pre[i] + g_boff[blockIdx.x];
        g_fill[i]   = 0;
    }
}

// ---------------- CSR fill (src index only; norm folded into features) ------
__global__ void gnn_csr_fill(const void* __restrict__ edges) {
    int e = blockIdx.x * blockDim.x + threadIdx.x;
    if (e < N_EDGES) {
        int s = edge_at(edges, e);
        int d = edge_at(edges, (long long)N_EDGES + e);
        int slot = g_rowptr[d] + atomicAdd(&g_fill[d], 1);
        g_csrc[slot] = s;
    }
}

// ---------------- linear (+ optional bias+relu on input), writes hs fp16 ----
// hs[v] = (relu(in[v]+b_prev) @ W) * dis[v], stored as half2 (lane-pair cols).
template <int K, bool PRE>
__global__ void gnn_linear(const float* __restrict__ in,
                           const float* __restrict__ W,
                           const float* __restrict__ bias_prev,
                           __half2* __restrict__ hs) {
    __shared__ float Wsh[K * HID];
    __shared__ float insh[32][K + 1];
    const int tid = threadIdx.x;
    for (int i = tid; i < K * HID; i += 256) Wsh[i] = W[i];

    const int base = blockIdx.x * 32;
    for (int i = tid; i < 32 * K; i += 256) {
        int vl = i / K;
        int k  = i - vl * K;
        int v  = base + vl;
        float val = 0.0f;
        if (v < N_NODES) {
            val = in[v * K + k];
            if (PRE) val = fmaxf(val + bias_prev[k], 0.0f);
        }
        insh[vl][k] = val;
    }
    __syncthreads();

    const int vl = tid >> 3;
    const int cb = (tid & 7) * 8;
    float acc[8];
#pragma unroll
    for (int j = 0; j < 8; j++) acc[j] = 0.0f;
#pragma unroll 16
    for (int k = 0; k < K; k++) {
        float a = insh[vl][k];
#pragma unroll
        for (int j = 0; j < 8; j++) acc[j] += a * Wsh[k * HID + cb + j];
    }
    const int v = base + vl;
    if (v < N_NODES) {
        float ds = g_dis[v];
#pragma unroll
        for (int j = 0; j < 4; j++) {
            hs[v * 32 + (cb >> 1) + j] =
                __floats2half2_rn(acc[2 * j] * ds, acc[2 * j + 1] * ds);
        }
    }
}

// ---------------- gather: agg[v] = dis[v] * (sum_e hs[src] + hs[v]) ----------
// One warp per destination node; lane owns 2 columns (half2 -> fp32 accum).
// 128B (one line) gathered per edge, 4B of index metadata per edge.
__global__ void __launch_bounds__(256) gnn_gather(const __half2* __restrict__ hs,
                                                  float2* __restrict__ agg2) {
    int warp = (blockIdx.x * blockDim.x + threadIdx.x) >> 5;
    int lane = threadIdx.x & 31;
    if (warp >= N_NODES) return;
    const int v   = warp;
    const int beg = g_rowptr[v];
    const int end = beg + g_edeg[v];

    float2 acc = __half22float2(hs[v * 32 + lane]);  // self term

    for (int base = beg; base < end; base += 32) {
        int s = 0;
        if (base + lane < end) s = g_csrc[base + lane];
        const int n_in = min(32, end - base);
#pragma unroll
        for (int j = 0; j < 32; j++) {
            if (j < n_in) {
                int ss = __shfl_sync(0xffffffffu, s, j);
                float2 hh = __half22float2(hs[ss * 32 + lane]);
                acc.x += hh.x;
                acc.y += hh.y;
            }
        }
    }
    float ds = g_dis[v];
    agg2[v * 32 + lane] = make_float2(acc.x * ds, acc.y * ds);
}

// ---------------- pooling ----------------------------------------------------
__global__ void gnn_zero_out(float* __restrict__ out) {
    int i = blockIdx.x * blockDim.x + threadIdx.x;
    if (i < NUM_GRAPHS * HID) out[i] = 0.0f;
    if (i < NUM_GRAPHS) g_cnt[i] = 0.0f;
}

__global__ void gnn_pool(const float4* __restrict__ agg,
                         const float4* __restrict__ bias4,
                         const void* __restrict__ batch,
                         float* __restrict__ out) {
    unsigned idx = blockIdx.x * blockDim.x + threadIdx.x;
    int v = idx >> 4;
    int c = idx & 15;
    if (v >= N_NODES) return;
    int g = batch_at(batch, v);
    float4 a = agg[v * 16 + c];
    float4 b = bias4[c];
    float x0 = fmaxf(a.x + b.x, 0.0f);
    float x1 = fmaxf(a.y + b.y, 0.0f);
    float x2 = fmaxf(a.z + b.z, 0.0f);
    float x3 = fmaxf(a.w + b.w, 0.0f);
    float* p = &out[g * HID + c * 4];
    asm volatile("red.global.add.v4.f32 [%0], {%1, %2, %3, %4};"
                 :: "l"(p), "f"(x0), "f"(x1), "f"(x2), "f"(x3)
                 : "memory");
    if (c == 0) atomicAdd(&g_cnt[g], 1.0f);
}

__global__ void gnn_div(float* __restrict__ out) {
    int i = blockIdx.x * blockDim.x + threadIdx.x;
    if (i < NUM_GRAPHS * HID) {
        int g = i >> 6;
        out[i] /= fmaxf(g_cnt[g], 1.0f);
    }
}

// ---------------- host -------------------------------------------------------
extern "C" void kernel_launch(void* const* d_in, const int* in_sizes, int n_in,
                              void* d_out, int out_size) {
    const float* x     = (const float*)d_in[0];
    const float* w1    = (const float*)d_in[1];
    const float* b1    = (const float*)d_in[2];
    const float* w2    = (const float*)d_in[3];
    const float* b2    = (const float*)d_in[4];
    const float* w3    = (const float*)d_in[5];
    const float* b3    = (const float*)d_in[6];
    const float* w4    = (const float*)d_in[7];
    const float* b4    = (const float*)d_in[8];
    const void*  edges = d_in[9];
    const void*  batch = d_in[10];
    float* out = (float*)d_out;

    void *p_hs, *p_aggA, *p_aggB;
    cudaGetSymbolAddress(&p_hs,   g_hs);
    cudaGetSymbolAddress(&p_aggA, g_aggA);
    cudaGetSymbolAddress(&p_aggB, g_aggB);
    __half2* hs  = (__half2*)p_hs;
    float*   aggA = (float*)p_aggA;
    float*   aggB = (float*)p_aggB;

    const int TB = 256;
    const int nodeB = (N_NODES + TB - 1) / TB;
    const int edgeB = (N_EDGES + TB - 1) / TB;

    // dtype detection + degree/norm + CSR build
    gnn_detect   <<<1, 256>>>(edges, batch);
    gnn_deg_zero <<<nodeB, TB>>>();
    gnn_deg_count<<<edgeB, TB>>>(edges);
    gnn_dis      <<<nodeB, TB>>>();
    gnn_scan1    <<<NBLK, 256>>>();
    gnn_scan2    <<<1, 512>>>();
    gnn_scan3    <<<NBLK, 256>>>();
    gnn_csr_fill <<<edgeB, TB>>>(edges);

    const int linB  = (N_NODES + 31) / 32;
    const int gatB  = (N_NODES * 32 + TB - 1) / TB;  // one warp per node

    // layer 1
    gnn_linear<IN_DIM, false><<<linB, TB>>>(x, w1, nullptr, hs);
    gnn_gather<<<gatB, TB>>>(hs, (float2*)aggA);
    // layer 2
    gnn_linear<HID, true><<<linB, TB>>>(aggA, w2, b1, hs);
    gnn_gather<<<gatB, TB>>>(hs, (float2*)aggB);
    // layer 3
    gnn_linear<HID, true><<<linB, TB>>>(aggB, w3, b2, hs);
    gnn_gather<<<gatB, TB>>>(hs, (float2*)aggA);
    // layer 4
    gnn_linear<HID, true><<<linB, TB>>>(aggA, w4, b3, hs);
    gnn_gather<<<gatB, TB>>>(hs, (float2*)aggB);

    // pooling: mean over relu(aggB + b4) per graph
    gnn_zero_out<<<(NUM_GRAPHS * HID + TB - 1) / TB, TB>>>(out);
    const unsigned poolT = (unsigned)N_NODES * 16u;
    gnn_pool<<<(int)((poolT + TB - 1) / TB), TB>>>(
        (const float4*)aggB, (const float4*)b4, batch, out);
    gnn_div<<<(NUM_GRAPHS * HID + TB - 1) / TB, TB>>>(out);
}

// round 5
// speedup vs baseline: 2.4214x; 1.7471x over previous
#include <cuda_runtime.h>
#include <cuda_fp16.h>

#define N_NODES    100000
#define N_EDGES    3200000
#define NUM_GRAPHS 128
#define HID        64
#define IN_DIM     15
#define NBLK       ((N_NODES + 255) / 256)   // scan blocks
#define NPB        96                        // nodes per linear block

// ---------------- scratch (device globals; no allocation allowed) -----------
// +1 zero pad row: out-of-range gather lanes read it (stays zero forever).
__device__ __align__(16) __half2 g_hs[(N_NODES + 1) * 32];
__device__ __align__(16) float   g_aggA[N_NODES * HID];
__device__ __align__(16) float   g_aggB[N_NODES * HID];
__device__ int   g_csrc [N_EDGES];   // CSR (by dst): source node per slot
__device__ int   g_edeg  [N_NODES];
__device__ int   g_pre   [N_NODES];
__device__ int   g_rowptr[N_NODES];
__device__ int   g_fill  [N_NODES];
__device__ int   g_bsum[NBLK];
__device__ int   g_boff[NBLK];
__device__ float g_dis[N_NODES];
__device__ float g_cnt[NUM_GRAPHS];
__device__ int   g_e32;
__device__ int   g_b32;

// ---------------- dtype detection -------------------------------------------
__global__ void gnn_detect(const void* edges, const void* batch) {
    __shared__ int se, sb;
    if (threadIdx.x == 0) { se = 0; sb = 0; }
    __syncthreads();
    for (int i = threadIdx.x; i < 2048; i += 256) {
        long long vi = (long long)i * (N_EDGES / 2048);
        long long v = ((const long long*)edges)[vi];
        if (v < 0 || v >= N_NODES) { atomicOr(&se, 1); break; }
    }
    for (int i = threadIdx.x; i < 2048; i += 256) {
        long long vi = (long long)i * ((N_NODES / 2) / 2048);
        long long v = ((const long long*)batch)[vi];
        if (v < 0 || v >= NUM_GRAPHS) { atomicOr(&sb, 1); break; }
    }
    __syncthreads();
    if (threadIdx.x == 0) { g_e32 = se; g_b32 = sb; }
}

__device__ __forceinline__ int edge_at(const void* edges, long long i) {
    return g_e32 ? ((const int*)edges)[i] : (int)((const long long*)edges)[i];
}
__device__ __forceinline__ int batch_at(const void* batch, int v) {
    return g_b32 ? ((const int*)batch)[v] : (int)((const long long*)batch)[v];
}

// ---------------- degree / normalization ------------------------------------
__global__ void gnn_deg_zero() {
    int v = blockIdx.x * blockDim.x + threadIdx.x;
    if (v < N_NODES) g_edeg[v] = 0;
    if (blockIdx.x == 0 && threadIdx.x < 32)   // zero the gather pad row
        g_hs[N_NODES * 32 + threadIdx.x] = __floats2half2_rn(0.0f, 0.0f);
}

__global__ void gnn_deg_count(const void* __restrict__ edges) {
    int e = blockIdx.x * blockDim.x + threadIdx.x;
    if (e < N_EDGES) {
        int d = edge_at(edges, (long long)N_EDGES + e);
        atomicAdd(&g_edeg[d], 1);
    }
}

__global__ void gnn_dis() {
    int v = blockIdx.x * blockDim.x + threadIdx.x;
    if (v < N_NODES) {
        float d = (float)(g_edeg[v] + 1);  // + self loop
        g_dis[v] = rsqrtf(d);
    }
}

// ---------------- exclusive scan of g_edeg -> g_rowptr -----------------------
__global__ void gnn_scan1() {
    __shared__ int s[256];
    int t = threadIdx.x;
    int i = blockIdx.x * 256 + t;
    int v = (i < N_NODES) ? g_edeg[i] : 0;
    s[t] = v; __syncthreads();
    for (int off = 1; off < 256; off <<= 1) {
        int add = (t >= off) ? s[t - off] : 0;
        __syncthreads();
        s[t] += add;
        __syncthreads();
    }
    if (i < N_NODES) g_pre[i] = s[t] - v;
    if (t == 255) g_bsum[blockIdx.x] = s[255];
}

__global__ void gnn_scan2() {
    __shared__ int s[512];
    int t = threadIdx.x;
    int v = (t < NBLK) ? g_bsum[t] : 0;
    s[t] = v; __syncthreads();
    for (int off = 1; off < 512; off <<= 1) {
        int add = (t >= off) ? s[t - off] : 0;
        __syncthreads();
        s[t] += add;
        __syncthreads();
    }
    if (t < NBLK) g_boff[t] = s[t] - v;
}

__global__ void gnn_scan3() {
    int i = blockIdx.x * blockDim.x + threadIdx.x;
    if (i < N_NODES) {
        g_rowptr[i] = g_pre[i] + g_boff[blockIdx.x];
        g_fill[i]   = 0;
    }
}

// ---------------- CSR fill ----------------------------------------------------
__global__ void gnn_csr_fill(const void* __restrict__ edges) {
    int e = blockIdx.x * blockDim.x + threadIdx.x;
    if (e < N_EDGES) {
        int s = edge_at(edges, e);
        int d = edge_at(edges, (long long)N_EDGES + e);
        int slot = g_rowptr[d] + atomicAdd(&g_fill[d], 1);
        g_csrc[slot] = s;
    }
}

// ---------------- linear: hs[v] = (relu(in+b_prev) @ W) * dis[v], fp16 -------
// 256 threads, 96 nodes/block, 3 nodes per thread, 8 cols per thread.
// insh transposed [k][node] with stride 97 (conflict-free); W read as float4.
template <int K, bool PRE>
__global__ void __launch_bounds__(256) gnn_linear(const float* __restrict__ in,
                                                  const float* __restrict__ W,
                                                  const float* __restrict__ bias_prev,
                                                  __half2* __restrict__ hs) {
    __shared__ float Wsh[K * HID];
    __shared__ float insh[K * 97];
    __shared__ float bsh[K];
    const int tid  = threadIdx.x;
    const int base = blockIdx.x * NPB;

    for (int i = tid; i < K * HID; i += 256) Wsh[i] = W[i];
    if (PRE) for (int i = tid; i < K; i += 256) bsh[i] = bias_prev[i];
    __syncthreads();

    // fill insh[k][n] from in[(base+n)*K + k]; i -> (n = i/K, k = i%K) keeps
    // gmem reads coalesced and smem writes conflict-free (stride 97).
    for (int i = tid; i < NPB * K; i += 256) {
        int n = i / K;
        int k = i - n * K;
        int v = base + n;
        float val = 0.0f;
        if (v < N_NODES) {
            val = in[v * K + k];
            if (PRE) val = fmaxf(val + bsh[k], 0.0f);
        }
        insh[k * 97 + n] = val;
    }
    __syncthreads();

    const int ng = tid >> 3;          // 0..31 node groups of 3
    const int cb = (tid & 7) * 8;     // col block
    float acc[3][8];
#pragma unroll
    for (int i = 0; i < 3; i++)
#pragma unroll
        for (int j = 0; j < 8; j++) acc[i][j] = 0.0f;

#pragma unroll 8
    for (int k = 0; k < K; k++) {
        float4 w0 = *(const float4*)&Wsh[k * HID + cb];
        float4 w1 = *(const float4*)&Wsh[k * HID + cb + 4];
#pragma unroll
        for (int i = 0; i < 3; i++) {
            float a = insh[k * 97 + ng * 3 + i];
            acc[i][0] = fmaf(a, w0.x, acc[i][0]);
            acc[i][1] = fmaf(a, w0.y, acc[i][1]);
            acc[i][2] = fmaf(a, w0.z, acc[i][2]);
            acc[i][3] = fmaf(a, w0.w, acc[i][3]);
            acc[i][4] = fmaf(a, w1.x, acc[i][4]);
            acc[i][5] = fmaf(a, w1.y, acc[i][5]);
            acc[i][6] = fmaf(a, w1.z, acc[i][6]);
            acc[i][7] = fmaf(a, w1.w, acc[i][7]);
        }
    }

#pragma unroll
    for (int i = 0; i < 3; i++) {
        int v = base + ng * 3 + i;
        if (v < N_NODES) {
            float ds = g_dis[v];
#pragma unroll
            for (int j = 0; j < 4; j++) {
                hs[v * 32 + (cb >> 1) + j] =
                    __floats2half2_rn(acc[i][2 * j] * ds, acc[i][2 * j + 1] * ds);
            }
        }
    }
}

// ---------------- gather: agg[v] = dis[v] * (sum_e hs[src] + hs[v]) ----------
// One warp per node, lane owns 2 cols. Branch-free inner loop: OOB lanes read
// the zero pad row (single hot line).
__global__ void __launch_bounds__(256) gnn_gather(const __half2* __restrict__ hs,
                                                  float2* __restrict__ agg2) {
    int warp = (blockIdx.x * blockDim.x + threadIdx.x) >> 5;
    int lane = threadIdx.x & 31;
    if (warp >= N_NODES) return;
    const int v   = warp;
    const int beg = g_rowptr[v];
    const int end = beg + g_edeg[v];

    float2 acc = __half22float2(hs[v * 32 + lane]);  // self term

    for (int base = beg; base < end; base += 32) {
        int idx = base + lane;
        int s = (idx < end) ? g_csrc[idx] : N_NODES;  // pad row if OOB
#pragma unroll
        for (int j = 0; j < 32; j++) {
            int ss = __shfl_sync(0xffffffffu, s, j);
            float2 hh = __half22float2(hs[ss * 32 + lane]);
            acc.x += hh.x;
            acc.y += hh.y;
        }
    }
    float ds = g_dis[v];
    agg2[v * 32 + lane] = make_float2(acc.x * ds, acc.y * ds);
}

// ---------------- pooling ----------------------------------------------------
__global__ void gnn_zero_out(float* __restrict__ out) {
    int i = blockIdx.x * blockDim.x + threadIdx.x;
    if (i < NUM_GRAPHS * HID) out[i] = 0.0f;
    if (i < NUM_GRAPHS) g_cnt[i] = 0.0f;
}

__global__ void gnn_pool(const float4* __restrict__ agg,
                         const float4* __restrict__ bias4,
                         const void* __restrict__ batch,
                         float* __restrict__ out) {
    unsigned idx = blockIdx.x * blockDim.x + threadIdx.x;
    int v = idx >> 4;
    int c = idx & 15;
    if (v >= N_NODES) return;
    int g = batch_at(batch, v);
    float4 a = agg[v * 16 + c];
    float4 b = bias4[c];
    float x0 = fmaxf(a.x + b.x, 0.0f);
    float x1 = fmaxf(a.y + b.y, 0.0f);
    float x2 = fmaxf(a.z + b.z, 0.0f);
    float x3 = fmaxf(a.w + b.w, 0.0f);
    float* p = &out[g * HID + c * 4];
    asm volatile("red.global.add.v4.f32 [%0], {%1, %2, %3, %4};"
                 :: "l"(p), "f"(x0), "f"(x1), "f"(x2), "f"(x3)
                 : "memory");
    if (c == 0) atomicAdd(&g_cnt[g], 1.0f);
}

__global__ void gnn_div(float* __restrict__ out) {
    int i = blockIdx.x * blockDim.x + threadIdx.x;
    if (i < NUM_GRAPHS * HID) {
        int g = i >> 6;
        out[i] /= fmaxf(g_cnt[g], 1.0f);
    }
}

// ---------------- host -------------------------------------------------------
extern "C" void kernel_launch(void* const* d_in, const int* in_sizes, int n_in,
                              void* d_out, int out_size) {
    const float* x     = (const float*)d_in[0];
    const float* w1    = (const float*)d_in[1];
    const float* b1    = (const float*)d_in[2];
    const float* w2    = (const float*)d_in[3];
    const float* b2    = (const float*)d_in[4];
    const float* w3    = (const float*)d_in[5];
    const float* b3    = (const float*)d_in[6];
    const float* w4    = (const float*)d_in[7];
    const float* b4    = (const float*)d_in[8];
    const void*  edges = d_in[9];
    const void*  batch = d_in[10];
    float* out = (float*)d_out;

    void *p_hs, *p_aggA, *p_aggB;
    cudaGetSymbolAddress(&p_hs,   g_hs);
    cudaGetSymbolAddress(&p_aggA, g_aggA);
    cudaGetSymbolAddress(&p_aggB, g_aggB);
    __half2* hs   = (__half2*)p_hs;
    float*   aggA = (float*)p_aggA;
    float*   aggB = (float*)p_aggB;

    const int TB = 256;
    const int nodeB = (N_NODES + TB - 1) / TB;
    const int edgeB = (N_EDGES + TB - 1) / TB;

    gnn_detect   <<<1, 256>>>(edges, batch);
    gnn_deg_zero <<<nodeB, TB>>>();
    gnn_deg_count<<<edgeB, TB>>>(edges);
    gnn_dis      <<<nodeB, TB>>>();
    gnn_scan1    <<<NBLK, 256>>>();
    gnn_scan2    <<<1, 512>>>();
    gnn_scan3    <<<NBLK, 256>>>();
    gnn_csr_fill <<<edgeB, TB>>>(edges);

    const int linB = (N_NODES + NPB - 1) / NPB;
    const int gatB = (N_NODES * 32 + TB - 1) / TB;

    // layer 1
    gnn_linear<IN_DIM, false><<<linB, TB>>>(x, w1, nullptr, hs);
    gnn_gather<<<gatB, TB>>>(hs, (float2*)aggA);
    // layer 2
    gnn_linear<HID, true><<<linB, TB>>>(aggA, w2, b1, hs);
    gnn_gather<<<gatB, TB>>>(hs, (float2*)aggB);
    // layer 3
    gnn_linear<HID, true><<<linB, TB>>>(aggB, w3, b2, hs);
    gnn_gather<<<gatB, TB>>>(hs, (float2*)aggA);
    // layer 4
    gnn_linear<HID, true><<<linB, TB>>>(aggA, w4, b3, hs);
    gnn_gather<<<gatB, TB>>>(hs, (float2*)aggB);

    // pooling
    gnn_zero_out<<<(NUM_GRAPHS * HID + TB - 1) / TB, TB>>>(out);
    const unsigned poolT = (unsigned)N_NODES * 16u;
    gnn_pool<<<(int)((poolT + TB - 1) / TB), TB>>>(
        (const float4*)aggB, (const float4*)b4, batch, out);
    gnn_div<<<(NUM_GRAPHS * HID + TB - 1) / TB, TB>>>(out);
}